// round 1
// baseline (speedup 1.0000x reference)
#include <cuda_runtime.h>
#include <math.h>
#include <stdint.h>

// Problem dims (fixed for this benchmark)
#define B_ 128
#define N_ 4096
#define H_ 128
#define P_ 128
#define LDS_ 132          // padded smem row stride (floats) -> conflict-free
#define NEGC (-10000.0f)

// Scratch (allocation-free rule: __device__ globals)
__device__ float g_scales[3];            // sv, sq, sa
__device__ float g_qproj[B_ * P_];       // q @ Wq_n^T + bq
__device__ float g_logits[(size_t)B_ * N_];

// ---------------------------------------------------------------------------
// Kernel 0: weight-norm scale factors  s = g / ||W||_F
// ---------------------------------------------------------------------------
__global__ void prep_scales_kernel(const float* __restrict__ Wv,
                                   const float* __restrict__ Wq,
                                   const float* __restrict__ Wa,
                                   const float* __restrict__ gv,
                                   const float* __restrict__ gq,
                                   const float* __restrict__ ga) {
    __shared__ float red[8];
    __shared__ float tot[3];
    int t = threadIdx.x;
    float s0 = 0.f, s1 = 0.f, s2 = 0.f;
    for (int i = t; i < P_ * H_; i += 256) {
        float a = Wv[i]; s0 += a * a;
        float c = Wq[i]; s1 += c * c;
    }
    if (t < P_) { float a = Wa[t]; s2 = a * a; }
    float s[3] = {s0, s1, s2};
    for (int j = 0; j < 3; j++) {
        float x = s[j];
        #pragma unroll
        for (int o = 16; o; o >>= 1) x += __shfl_xor_sync(0xFFFFFFFFu, x, o);
        if ((t & 31) == 0) red[t >> 5] = x;
        __syncthreads();
        if (t == 0) {
            float r = 0.f;
            for (int w = 0; w < 8; w++) r += red[w];
            tot[j] = r;
        }
        __syncthreads();
    }
    if (t == 0) {
        g_scales[0] = gv[0] / sqrtf(tot[0]);
        g_scales[1] = gq[0] / sqrtf(tot[1]);
        g_scales[2] = ga[0] / sqrtf(tot[2]);
    }
}

// ---------------------------------------------------------------------------
// Kernel 1: q_proj[b,p] = sq * dot(q[b,:], Wq[p,:]) + bq[p]
// ---------------------------------------------------------------------------
__global__ void qproj_kernel(const float* __restrict__ q,
                             const float* __restrict__ Wq,
                             const float* __restrict__ bq) {
    int b = blockIdx.x;
    int p = threadIdx.x;
    float sq = g_scales[1];
    const float* qb = q + b * H_;
    const float* wp = Wq + p * H_;
    float acc = 0.f;
    #pragma unroll 8
    for (int h = 0; h < H_; h++) acc += qb[h] * wp[h];
    g_qproj[b * P_ + p] = sq * acc + bq[p];
}

// ---------------------------------------------------------------------------
// tf32 helpers
// ---------------------------------------------------------------------------
__device__ __forceinline__ float f2tf(float x) {
    uint32_t r;
    asm("cvt.rna.tf32.f32 %0, %1;" : "=r"(r) : "f"(x));
    return __uint_as_float(r);
}

__device__ __forceinline__ void mma_tf32(float* d,
                                         uint32_t a0, uint32_t a1, uint32_t a2, uint32_t a3,
                                         uint32_t b0, uint32_t b1) {
    asm volatile(
        "mma.sync.aligned.m16n8k8.row.col.f32.tf32.tf32.f32 "
        "{%0,%1,%2,%3}, {%4,%5,%6,%7}, {%8,%9}, {%0,%1,%2,%3};"
        : "+f"(d[0]), "+f"(d[1]), "+f"(d[2]), "+f"(d[3])
        : "r"(a0), "r"(a1), "r"(a2), "r"(a3), "r"(b0), "r"(b1));
}

// ---------------------------------------------------------------------------
// Kernel 2: fused  v_proj -> relu -> logits -> online softmax -> att
// One CTA per batch row b. 256 threads = 8 warps. Each warp owns 16 rows of
// the 128-row v tile; tf32 mma computes the 128x128 (rows x P) projection.
// ---------------------------------------------------------------------------
__global__ void __launch_bounds__(256, 1)
main_kernel(const float* __restrict__ v,
            const float* __restrict__ mask,
            const float* __restrict__ Wv,
            const float* __restrict__ bv,
            const float* __restrict__ Wa,
            const float* __restrict__ ba,
            float* __restrict__ out_att,
            float* __restrict__ out_w) {
    const int b    = blockIdx.x;
    const int tid  = threadIdx.x;
    const int warp = tid >> 5;
    const int lane = tid & 31;
    const int g    = lane >> 2;   // group id 0..7
    const int t4   = lane & 3;    // thread in group 0..3

    extern __shared__ float sm[];
    float* Ws   = sm;                     // P_ x LDS_   (tf32-rounded, * sv)
    float* Vs   = Ws + P_ * LDS_;         // 128 x LDS_  (tf32-rounded tile)
    float* qp   = Vs + 128 * LDS_;        // P_   (q_proj + bv)
    float* was  = qp + P_;                // P_   (sa * Wa)
    float* lg   = was + P_;               // 128 logits of current tile
    float* we   = lg + 128;               // 128 exp weights
    float* bc   = we + 128;               // 16 reduce slots
    float* attc = bc + 16;                // 256 att-partial combine

    const float sv = g_scales[0];
    const float sa = g_scales[2];
    const float ba0 = ba[0];

    // Resident weights: pre-scale + tf32-round once per CTA
    for (int i = tid; i < P_ * H_; i += 256) {
        int p = i >> 7, h = i & 127;
        Ws[p * LDS_ + h] = f2tf(sv * Wv[i]);
    }
    for (int i = tid; i < P_; i += 256) {
        qp[i]  = g_qproj[b * P_ + i] + bv[i];
        was[i] = sa * Wa[i];
    }

    float M = -INFINITY;   // running max
    float S = 0.f;         // running exp-sum
    float attp = 0.f;      // per-thread att partial for h_own, row-half
    const int h_own = tid & 127;
    const int rbase = (tid >> 7) * 64;

    __syncthreads();

    const int m0 = warp * 16;

    for (int n0 = 0; n0 < N_; n0 += 128) {
        // ---- load v tile (128 x 128 fp32), tf32-round into smem ----
        const float* vsrc = v + ((size_t)b * N_ + n0) * H_;
        for (int i = tid; i < 128 * (H_ / 4); i += 256) {
            int row = i >> 5;        // H_/4 = 32
            int c4  = i & 31;
            float4 val = __ldg((const float4*)vsrc + (size_t)row * 32 + c4);
            float4 cv;
            cv.x = f2tf(val.x); cv.y = f2tf(val.y);
            cv.z = f2tf(val.z); cv.w = f2tf(val.w);
            *(float4*)&Vs[row * LDS_ + c4 * 4] = cv;
        }
        __syncthreads();

        // ---- GEMM: this warp computes rows [m0, m0+16) x P_=128 ----
        float acc[16][4];
        #pragma unroll
        for (int nt = 0; nt < 16; nt++) {
            acc[nt][0] = 0.f; acc[nt][1] = 0.f; acc[nt][2] = 0.f; acc[nt][3] = 0.f;
        }
        #pragma unroll 2
        for (int k = 0; k < 16; k++) {
            const int k0 = k * 8;
            uint32_t a0 = __float_as_uint(Vs[(m0 + g) * LDS_ + k0 + t4]);
            uint32_t a1 = __float_as_uint(Vs[(m0 + g + 8) * LDS_ + k0 + t4]);
            uint32_t a2 = __float_as_uint(Vs[(m0 + g) * LDS_ + k0 + t4 + 4]);
            uint32_t a3 = __float_as_uint(Vs[(m0 + g + 8) * LDS_ + k0 + t4 + 4]);
            #pragma unroll
            for (int nt = 0; nt < 16; nt++) {
                const int p0 = nt * 8;
                uint32_t b0 = __float_as_uint(Ws[(p0 + g) * LDS_ + k0 + t4]);
                uint32_t b1 = __float_as_uint(Ws[(p0 + g) * LDS_ + k0 + t4 + 4]);
                mma_tf32(acc[nt], a0, a1, a2, a3, b0, b1);
            }
        }

        // ---- epilogue: relu + dot with wa -> per-row logit partials ----
        float pl0 = 0.f, pl1 = 0.f;
        #pragma unroll
        for (int nt = 0; nt < 16; nt++) {
            const int p0 = nt * 8 + 2 * t4;
            float q0 = qp[p0], q1 = qp[p0 + 1];
            float w0 = was[p0], w1 = was[p0 + 1];
            pl0 += fmaxf(acc[nt][0] + q0, 0.f) * w0 + fmaxf(acc[nt][1] + q1, 0.f) * w1;
            pl1 += fmaxf(acc[nt][2] + q0, 0.f) * w0 + fmaxf(acc[nt][3] + q1, 0.f) * w1;
        }
        pl0 += __shfl_xor_sync(0xFFFFFFFFu, pl0, 1);
        pl0 += __shfl_xor_sync(0xFFFFFFFFu, pl0, 2);
        pl1 += __shfl_xor_sync(0xFFFFFFFFu, pl1, 1);
        pl1 += __shfl_xor_sync(0xFFFFFFFFu, pl1, 2);
        if (t4 == 0) {
            const int r0 = m0 + g, r1 = m0 + g + 8;
            float l0 = pl0 + ba0 + (1.f - mask[(size_t)b * N_ + n0 + r0]) * NEGC;
            float l1 = pl1 + ba0 + (1.f - mask[(size_t)b * N_ + n0 + r1]) * NEGC;
            lg[r0] = l0; lg[r1] = l1;
            g_logits[(size_t)b * N_ + n0 + r0] = l0;
            g_logits[(size_t)b * N_ + n0 + r1] = l1;
        }
        __syncthreads();

        // ---- tile max reduce ----
        float x = (tid < 128) ? lg[tid] : -INFINITY;
        #pragma unroll
        for (int o = 16; o; o >>= 1) x = fmaxf(x, __shfl_xor_sync(0xFFFFFFFFu, x, o));
        if (lane == 0) bc[warp] = x;
        __syncthreads();
        float tm = bc[0];
        #pragma unroll
        for (int w = 1; w < 8; w++) tm = fmaxf(tm, bc[w]);
        float Mn = fmaxf(M, tm);
        float r  = __expf(M - Mn);   // 0 on first tile (M = -inf)

        // ---- exp + tile sum ----
        float e = 0.f;
        if (tid < 128) { e = __expf(lg[tid] - Mn); we[tid] = e; }
        #pragma unroll
        for (int o = 16; o; o >>= 1) e += __shfl_xor_sync(0xFFFFFFFFu, e, o);
        if (lane == 0) bc[8 + warp] = e;
        __syncthreads();
        float tsum = 0.f;
        #pragma unroll
        for (int w = 0; w < 8; w++) tsum += bc[8 + w];
        S = S * r + tsum;
        M = Mn;

        // ---- att partial update (v tile still in smem) ----
        float a_ = attp * r;
        #pragma unroll 8
        for (int row = rbase; row < rbase + 64; row++) {
            a_ += we[row] * Vs[row * LDS_ + h_own];
        }
        attp = a_;
        __syncthreads();   // before next tile overwrites Vs / lg
    }

    // ---- final: combine halves, normalize, write outputs ----
    attc[tid] = attp;
    __syncthreads();
    const float invS = 1.f / S;
    if (tid < 128) {
        out_att[b * H_ + tid] = (attc[tid] + attc[tid + 128]) * invS;
    }
    for (int n = tid; n < N_; n += 256) {
        out_w[(size_t)b * N_ + n] = __expf(g_logits[(size_t)b * N_ + n] - M) * invS;
    }
}

// ---------------------------------------------------------------------------
// Launch
// ---------------------------------------------------------------------------
extern "C" void kernel_launch(void* const* d_in, const int* in_sizes, int n_in,
                              void* d_out, int out_size) {
    const float* v    = (const float*)d_in[0];
    const float* q    = (const float*)d_in[1];
    const float* mask = (const float*)d_in[2];
    const float* Wv   = (const float*)d_in[3];
    const float* bv   = (const float*)d_in[4];
    const float* gv   = (const float*)d_in[5];
    const float* Wq   = (const float*)d_in[6];
    const float* bq   = (const float*)d_in[7];
    const float* gq   = (const float*)d_in[8];
    const float* Wa   = (const float*)d_in[9];
    const float* ba   = (const float*)d_in[10];
    const float* ga   = (const float*)d_in[11];

    float* out     = (float*)d_out;
    float* out_att = out;              // [B, H]
    float* out_w   = out + B_ * H_;    // [B, N, 1]

    // smem: Ws + Vs + qp + was + lg + we + bc + attc
    const int smem_bytes = (P_ * LDS_ + 128 * LDS_ + P_ + P_ + 128 + 128 + 16 + 256) * sizeof(float);
    cudaFuncSetAttribute(main_kernel, cudaFuncAttributeMaxDynamicSharedMemorySize, smem_bytes);

    prep_scales_kernel<<<1, 256>>>(Wv, Wq, Wa, gv, gq, ga);
    qproj_kernel<<<B_, 128>>>(q, Wq, bq);
    main_kernel<<<B_, 256, smem_bytes>>>(v, mask, Wv, bv, Wa, ba, out_att, out_w);
}

// round 2
// speedup vs baseline: 1.3721x; 1.3721x over previous
#include <cuda_runtime.h>
#include <math.h>
#include <stdint.h>

#define B_ 128
#define N_ 4096
#define H_ 128
#define P_ 128
#define LDSV 132                 // padded v-tile row stride (floats)
#define NEGC (-10000.0f)
#define NTILES (N_ / 128)
#define THREADS 512

// __device__ scratch (allocation-free rule)
__device__ float g_scales[3];                 // sv, sq, sa
__device__ float g_logits[(size_t)B_ * N_];

// ---------------------------------------------------------------------------
// smem layout (floats)
// ---------------------------------------------------------------------------
#define OFF_WP    0                 // 16 nt * 16 k * 32 lanes * float2 = 16384 f
#define OFF_VS0   16384             // 128 * 132 = 16896 f
#define OFF_VS1   (16384 + 16896)   // 16896 f
#define OFF_QPW   (OFF_VS1 + 16896) // 128
#define OFF_WAS   (OFF_QPW + 128)   // 128
#define OFF_LG    (OFF_WAS + 128)   // 128
#define OFF_WE    (OFF_LG + 128)    // 128
#define OFF_LGP   (OFF_WE + 128)    // 512
#define OFF_BC    (OFF_LGP + 512)   // 32
#define OFF_ATTC  (OFF_BC + 32)     // 512
#define SMEM_FLOATS (OFF_ATTC + 512)

// ---------------------------------------------------------------------------
// Kernel 0: weight-norm scales s = g / ||W||_F  (one fast block)
// ---------------------------------------------------------------------------
__global__ void prep_scales_kernel(const float* __restrict__ Wv,
                                   const float* __restrict__ Wq,
                                   const float* __restrict__ Wa,
                                   const float* __restrict__ gv,
                                   const float* __restrict__ gq,
                                   const float* __restrict__ ga) {
    __shared__ float r0[32], r1[32], r2[32];
    int t = threadIdx.x;  // 1024
    float s0 = 0.f, s1 = 0.f;
    for (int i = t; i < P_ * H_; i += 1024) {
        float a = Wv[i]; s0 += a * a;
        float c = Wq[i]; s1 += c * c;
    }
    float s2 = (t < P_) ? Wa[t] * Wa[t] : 0.f;
    #pragma unroll
    for (int o = 16; o; o >>= 1) {
        s0 += __shfl_xor_sync(0xFFFFFFFFu, s0, o);
        s1 += __shfl_xor_sync(0xFFFFFFFFu, s1, o);
        s2 += __shfl_xor_sync(0xFFFFFFFFu, s2, o);
    }
    int w = t >> 5;
    if ((t & 31) == 0) { r0[w] = s0; r1[w] = s1; r2[w] = s2; }
    __syncthreads();
    if (t == 0) {
        float a = 0.f, b = 0.f, c = 0.f;
        #pragma unroll
        for (int i = 0; i < 32; i++) { a += r0[i]; b += r1[i]; }
        #pragma unroll
        for (int i = 0; i < 4; i++) c += r2[i];
        g_scales[0] = gv[0] / sqrtf(a);
        g_scales[1] = gq[0] / sqrtf(b);
        g_scales[2] = ga[0] / sqrtf(c);
    }
}

// ---------------------------------------------------------------------------
// helpers
// ---------------------------------------------------------------------------
__device__ __forceinline__ float f2tf(float x) {
    uint32_t r;
    asm("cvt.rna.tf32.f32 %0, %1;" : "=r"(r) : "f"(x));
    return __uint_as_float(r);
}

__device__ __forceinline__ void mma_tf32(float* d,
                                         uint32_t a0, uint32_t a1, uint32_t a2, uint32_t a3,
                                         uint32_t b0, uint32_t b1) {
    asm volatile(
        "mma.sync.aligned.m16n8k8.row.col.f32.tf32.tf32.f32 "
        "{%0,%1,%2,%3}, {%4,%5,%6,%7}, {%8,%9}, {%0,%1,%2,%3};"
        : "+f"(d[0]), "+f"(d[1]), "+f"(d[2]), "+f"(d[3])
        : "r"(a0), "r"(a1), "r"(a2), "r"(a3), "r"(b0), "r"(b1));
}

__device__ __forceinline__ void cp16(uint32_t dst_smem, const void* src) {
    asm volatile("cp.async.cg.shared.global [%0], [%1], 16;\n"
                 :: "r"(dst_smem), "l"(src));
}
__device__ __forceinline__ void cp_commit() {
    asm volatile("cp.async.commit_group;\n" ::);
}
__device__ __forceinline__ void cp_wait1() {
    asm volatile("cp.async.wait_group 1;\n" ::);
}
__device__ __forceinline__ void cp_wait0() {
    asm volatile("cp.async.wait_group 0;\n" ::);
}

// ---------------------------------------------------------------------------
// Main fused kernel: one CTA per batch row, 512 threads (16 warps).
// Warp (mi, ni): rows [mi*32, mi*32+32), cols [ni*32, ni*32+32).
// Double-buffered cp.async v pipeline; online softmax; att accumulated from
// the raw fp32 v tile still resident in smem.
// ---------------------------------------------------------------------------
__global__ void __launch_bounds__(THREADS, 1)
main_kernel(const float* __restrict__ v,
            const float* __restrict__ q,
            const float* __restrict__ mask,
            const float* __restrict__ Wv,
            const float* __restrict__ bv,
            const float* __restrict__ Wq,
            const float* __restrict__ bq,
            const float* __restrict__ Wa,
            const float* __restrict__ ba,
            float* __restrict__ out_att,
            float* __restrict__ out_w) {
    const int b    = blockIdx.x;
    const int tid  = threadIdx.x;
    const int warp = tid >> 5;
    const int lane = tid & 31;
    const int g    = lane >> 2;
    const int t4   = lane & 3;
    const int mi   = warp & 3;   // row block
    const int ni   = warp >> 2;  // col block

    extern __shared__ float sm[];
    float* Wp   = sm + OFF_WP;
    float* qpw  = sm + OFF_QPW;
    float* was  = sm + OFF_WAS;
    float* lg   = sm + OFF_LG;
    float* we   = sm + OFF_WE;
    float* lgp  = sm + OFF_LGP;
    float* bc   = sm + OFF_BC;
    float* attc = sm + OFF_ATTC;
    const uint32_t smem_u32 = (uint32_t)__cvta_generic_to_shared(sm);

    const float sv  = g_scales[0];
    const float sq  = g_scales[1];
    const float sa  = g_scales[2];
    const float ba0 = ba[0];

    const float* vsrc = v + (size_t)b * N_ * H_;

    // ---- stage Wq into Vs1 (group 0), then tile0 into Vs0 (group 1) ----
    for (int chunk = tid; chunk < 4096; chunk += THREADS) {
        int row = chunk >> 5, c4 = chunk & 31;
        cp16(smem_u32 + (OFF_VS1 + row * LDSV + c4 * 4) * 4, Wq + row * H_ + c4 * 4);
    }
    cp_commit();
    for (int chunk = tid; chunk < 4096; chunk += THREADS) {
        int row = chunk >> 5, c4 = chunk & 31;
        cp16(smem_u32 + (OFF_VS0 + row * LDSV + c4 * 4) * 4, vsrc + row * H_ + c4 * 4);
    }
    cp_commit();

    // ---- pack weight fragments (gmem Wv -> smem float2), scale vectors ----
    for (int e = tid; e < 8192; e += THREADS) {
        int l  = e & 31;
        int k  = (e >> 5) & 15;
        int nt = e >> 9;
        int p  = nt * 8 + (l >> 2);
        int c  = k * 8 + (l & 3);
        float2 val;
        val.x = f2tf(sv * Wv[p * H_ + c]);
        val.y = f2tf(sv * Wv[p * H_ + c + 4]);
        ((float2*)Wp)[e] = val;
    }
    if (tid < P_) was[tid] = sa * Wa[tid];

    cp_wait1();          // Wq staged
    __syncthreads();

    // ---- q_proj from staged Wq ----
    if (tid < P_) {
        const float* qb = q + b * H_;
        const float* wrow = sm + OFF_VS1 + tid * LDSV;
        float acc = 0.f;
        #pragma unroll 8
        for (int h = 0; h < H_; h++) acc += qb[h] * wrow[h];
        qpw[tid] = sq * acc + bq[tid] + bv[tid];
    }
    __syncthreads();     // before pipeline overwrites Vs1

    float M = -INFINITY, S = 0.f, attp = 0.f;
    const int hown = tid & 127;
    const int rseg = (tid >> 7) * 32;

    for (int t = 0; t < NTILES; t++) {
        // ---- prefetch next tile ----
        if (t + 1 < NTILES) {
            const float* src = vsrc + (size_t)(t + 1) * 128 * H_;
            const int voff = ((t + 1) & 1) ? OFF_VS1 : OFF_VS0;
            for (int chunk = tid; chunk < 4096; chunk += THREADS) {
                int row = chunk >> 5, c4 = chunk & 31;
                cp16(smem_u32 + (voff + row * LDSV + c4 * 4) * 4, src + row * H_ + c4 * 4);
            }
            cp_commit();
            cp_wait1();
        } else {
            cp_wait0();
        }
        __syncthreads();
        const float* Vb = sm + ((t & 1) ? OFF_VS1 : OFF_VS0);

        // ---- GEMM: 32 rows x 32 cols per warp, tf32 mma ----
        float acc[2][4][4];
        #pragma unroll
        for (int m2 = 0; m2 < 2; m2++)
            #pragma unroll
            for (int n2 = 0; n2 < 4; n2++)
                #pragma unroll
                for (int j = 0; j < 4; j++) acc[m2][n2][j] = 0.f;

        #pragma unroll
        for (int k = 0; k < 16; k++) {
            const int k0 = k * 8;
            uint32_t a[2][4];
            #pragma unroll
            for (int m2 = 0; m2 < 2; m2++) {
                const int r0 = mi * 32 + m2 * 16 + g;
                a[m2][0] = __float_as_uint(f2tf(Vb[r0 * LDSV + k0 + t4]));
                a[m2][1] = __float_as_uint(f2tf(Vb[(r0 + 8) * LDSV + k0 + t4]));
                a[m2][2] = __float_as_uint(f2tf(Vb[r0 * LDSV + k0 + t4 + 4]));
                a[m2][3] = __float_as_uint(f2tf(Vb[(r0 + 8) * LDSV + k0 + t4 + 4]));
            }
            #pragma unroll
            for (int n2 = 0; n2 < 4; n2++) {
                float2 bf = ((const float2*)Wp)[((ni * 4 + n2) * 16 + k) * 32 + lane];
                uint32_t b0 = __float_as_uint(bf.x);
                uint32_t b1 = __float_as_uint(bf.y);
                mma_tf32(acc[0][n2], a[0][0], a[0][1], a[0][2], a[0][3], b0, b1);
                mma_tf32(acc[1][n2], a[1][0], a[1][1], a[1][2], a[1][3], b0, b1);
            }
        }

        // ---- epilogue: relu + wa dot -> per-row logit partials ----
        float pl[2][2] = {{0.f, 0.f}, {0.f, 0.f}};
        #pragma unroll
        for (int n2 = 0; n2 < 4; n2++) {
            const int p0 = (ni * 4 + n2) * 8 + 2 * t4;
            float q0 = qpw[p0], q1 = qpw[p0 + 1];
            float w0 = was[p0], w1 = was[p0 + 1];
            #pragma unroll
            for (int m2 = 0; m2 < 2; m2++) {
                pl[m2][0] += fmaxf(acc[m2][n2][0] + q0, 0.f) * w0
                           + fmaxf(acc[m2][n2][1] + q1, 0.f) * w1;
                pl[m2][1] += fmaxf(acc[m2][n2][2] + q0, 0.f) * w0
                           + fmaxf(acc[m2][n2][3] + q1, 0.f) * w1;
            }
        }
        #pragma unroll
        for (int m2 = 0; m2 < 2; m2++) {
            #pragma unroll
            for (int h2 = 0; h2 < 2; h2++) {
                pl[m2][h2] += __shfl_xor_sync(0xFFFFFFFFu, pl[m2][h2], 1);
                pl[m2][h2] += __shfl_xor_sync(0xFFFFFFFFu, pl[m2][h2], 2);
            }
        }
        if (t4 == 0) {
            const int rb = mi * 32;
            lgp[(rb + g) * 4 + ni]      = pl[0][0];
            lgp[(rb + g + 8) * 4 + ni]  = pl[0][1];
            lgp[(rb + 16 + g) * 4 + ni] = pl[1][0];
            lgp[(rb + 24 + g) * 4 + ni] = pl[1][1];
        }
        __syncthreads();

        // ---- combine partials + mask ----
        if (tid < 128) {
            float l = lgp[tid * 4] + lgp[tid * 4 + 1] + lgp[tid * 4 + 2] + lgp[tid * 4 + 3]
                    + ba0 + (1.f - mask[(size_t)b * N_ + t * 128 + tid]) * NEGC;
            lg[tid] = l;
            g_logits[(size_t)b * N_ + t * 128 + tid] = l;
        }
        __syncthreads();

        // ---- tile max ----
        float x = (tid < 128) ? lg[tid] : -INFINITY;
        #pragma unroll
        for (int o = 16; o; o >>= 1) x = fmaxf(x, __shfl_xor_sync(0xFFFFFFFFu, x, o));
        if (lane == 0 && warp < 4) bc[warp] = x;
        __syncthreads();
        float Mn = fmaxf(M, fmaxf(fmaxf(bc[0], bc[1]), fmaxf(bc[2], bc[3])));
        float r  = __expf(M - Mn);

        // ---- exp + tile sum ----
        float e = 0.f;
        if (tid < 128) { e = __expf(lg[tid] - Mn); we[tid] = e; }
        #pragma unroll
        for (int o = 16; o; o >>= 1) e += __shfl_xor_sync(0xFFFFFFFFu, e, o);
        if (lane == 0 && warp < 4) bc[8 + warp] = e;
        __syncthreads();
        S = S * r + (bc[8] + bc[9] + bc[10] + bc[11]);
        M = Mn;

        // ---- att partial update from raw v tile in smem ----
        float a_ = attp * r;
        #pragma unroll 8
        for (int row = rseg; row < rseg + 32; row++) {
            a_ += we[row] * Vb[row * LDSV + hown];
        }
        attp = a_;
        __syncthreads();   // buffer reuse + lg/we/bc reuse
    }

    // ---- finals ----
    attc[tid] = attp;
    __syncthreads();
    const float invS = 1.f / S;
    if (tid < 128) {
        out_att[b * H_ + tid] =
            (attc[tid] + attc[tid + 128] + attc[tid + 256] + attc[tid + 384]) * invS;
    }
    for (int n = tid; n < N_; n += THREADS) {
        out_w[(size_t)b * N_ + n] = __expf(g_logits[(size_t)b * N_ + n] - M) * invS;
    }
}

// ---------------------------------------------------------------------------
// Launch
// ---------------------------------------------------------------------------
extern "C" void kernel_launch(void* const* d_in, const int* in_sizes, int n_in,
                              void* d_out, int out_size) {
    const float* v    = (const float*)d_in[0];
    const float* q    = (const float*)d_in[1];
    const float* mask = (const float*)d_in[2];
    const float* Wv   = (const float*)d_in[3];
    const float* bv   = (const float*)d_in[4];
    const float* gv   = (const float*)d_in[5];
    const float* Wq   = (const float*)d_in[6];
    const float* bq   = (const float*)d_in[7];
    const float* gq   = (const float*)d_in[8];
    const float* Wa   = (const float*)d_in[9];
    const float* ba   = (const float*)d_in[10];
    const float* ga   = (const float*)d_in[11];

    float* out     = (float*)d_out;
    float* out_att = out;              // [B, H]
    float* out_w   = out + B_ * H_;    // [B, N, 1]

    const int smem_bytes = SMEM_FLOATS * sizeof(float);
    static int attr_set = 0;
    cudaFuncSetAttribute(main_kernel, cudaFuncAttributeMaxDynamicSharedMemorySize, smem_bytes);
    (void)attr_set;

    prep_scales_kernel<<<1, 1024>>>(Wv, Wq, Wa, gv, gq, ga);
    main_kernel<<<B_, THREADS, smem_bytes>>>(v, q, mask, Wv, bv, Wq, bq, Wa, ba,
                                             out_att, out_w);
}

// round 4
// speedup vs baseline: 1.8003x; 1.3120x over previous
#include <cuda_runtime.h>
#include <math.h>
#include <stdint.h>

#define B_ 128
#define N_ 4096
#define H_ 128
#define P_ 128
#define NTILES 32
#define THREADS 128
#define NEGC (-10000.0f)

// padded row stride: 132 floats = 528 bytes (33*16B -> LDSM conflict-free)
#define LDSF 132
#define LDSB 528

// ---------------- smem layout (float offsets) ----------------
#define F_W     0                      // 128*132 = 16896
#define F_V0    16896                  // 16896
#define F_V1    (F_V0 + 16896)         // 16896
#define F_LSM   (F_V1 + 16896)         // 4096 logits
#define F_QW    (F_LSM + 4096)         // 256 (float2 qwas[128])
#define F_WE    (F_QW + 256)           // 128
#define F_LGP   (F_WE + 128)           // 256
#define F_BC    (F_LGP + 256)          // 16
#define F_RED   (F_BC + 16)            // 16
#define F_SCL   (F_RED + 16)           // 4
#define F_QROW  (F_SCL + 4)            // 128
#define SMEM_FLOATS (F_QROW + 128)     // ~55.6K floats = ~222.4 KB

// ---------------- helpers ----------------
__device__ __forceinline__ float f2tf(float x) {
    uint32_t r;
    asm("cvt.rna.tf32.f32 %0, %1;" : "=r"(r) : "f"(x));
    return __uint_as_float(r);
}

__device__ __forceinline__ void mma_tf32(float* d,
                                         uint32_t a0, uint32_t a1, uint32_t a2, uint32_t a3,
                                         uint32_t b0, uint32_t b1) {
    asm volatile(
        "mma.sync.aligned.m16n8k8.row.col.f32.tf32.tf32.f32 "
        "{%0,%1,%2,%3}, {%4,%5,%6,%7}, {%8,%9}, {%0,%1,%2,%3};"
        : "+f"(d[0]), "+f"(d[1]), "+f"(d[2]), "+f"(d[3])
        : "r"(a0), "r"(a1), "r"(a2), "r"(a3), "r"(b0), "r"(b1));
}

__device__ __forceinline__ void ldsm4(uint32_t* r, uint32_t addr) {
    asm volatile("ldmatrix.sync.aligned.m8n8.x4.shared.b16 {%0,%1,%2,%3}, [%4];"
                 : "=r"(r[0]), "=r"(r[1]), "=r"(r[2]), "=r"(r[3]) : "r"(addr));
}

__device__ __forceinline__ void cp16(uint32_t dst, const void* src) {
    asm volatile("cp.async.cg.shared.global [%0], [%1], 16;" :: "r"(dst), "l"(src));
}
__device__ __forceinline__ void cp_commit() { asm volatile("cp.async.commit_group;" ::); }
__device__ __forceinline__ void cp_wait1()  { asm volatile("cp.async.wait_group 1;" ::); }
__device__ __forceinline__ void cp_wait0()  { asm volatile("cp.async.wait_group 0;" ::); }

// ---------------------------------------------------------------------------
// One CTA per batch row. 128 threads = 4 warps, each warp owns a 64x64 block
// of the 128x128 (rows x P) projection. ldmatrix-fed tf32 mma, cp.async
// double-buffered V, online softmax, smem-resident logits.
// ---------------------------------------------------------------------------
__global__ void __launch_bounds__(THREADS, 1)
main_kernel(const float* __restrict__ v,
            const float* __restrict__ q,
            const float* __restrict__ mask,
            const float* __restrict__ Wv,
            const float* __restrict__ bv,
            const float* __restrict__ gv,
            const float* __restrict__ Wq,
            const float* __restrict__ bq,
            const float* __restrict__ gq,
            const float* __restrict__ Wa,
            const float* __restrict__ ba,
            const float* __restrict__ ga,
            float* __restrict__ out_att,
            float* __restrict__ out_w) {
    const int b    = blockIdx.x;
    const int tid  = threadIdx.x;
    const int warp = tid >> 5;
    const int lane = tid & 31;
    const int t4   = lane & 3;
    const int mi   = warp & 1;    // row half
    const int ni   = warp >> 1;   // col half

    extern __shared__ float sm[];
    const uint32_t sb = (uint32_t)__cvta_generic_to_shared(sm);
    float*  lsm  = sm + F_LSM;
    float2* qwas = (float2*)(sm + F_QW);
    float*  we   = sm + F_WE;
    float*  lgp  = sm + F_LGP;
    float*  bc   = sm + F_BC;
    float*  red  = sm + F_RED;
    float*  scl  = sm + F_SCL;
    float*  qrow = sm + F_QROW;

    const float* vsrc = v + (size_t)b * N_ * H_;

    // ---- group 0: Wq -> V1 staging; group 1: v tile0 -> V0 ----
    for (int i = tid; i < 4096; i += THREADS) {
        int row = i >> 5, c4 = i & 31;
        cp16(sb + (F_V1 + row * LDSF) * 4 + c4 * 16, Wq + row * H_ + c4 * 4);
    }
    cp_commit();
    for (int i = tid; i < 4096; i += THREADS) {
        int row = i >> 5, c4 = i & 31;
        cp16(sb + (F_V0 + row * LDSF) * 4 + c4 * 16, vsrc + row * H_ + c4 * 4);
    }
    cp_commit();

    // ---- norms for Wv, Wa; stage q row ----
    float s0 = 0.f;
    for (int i = tid; i < 4096; i += THREADS) {
        float4 a = __ldg((const float4*)Wv + i);
        s0 += a.x * a.x + a.y * a.y + a.z * a.z + a.w * a.w;
    }
    const float wa_own = __ldg(&Wa[tid]);
    float s2 = wa_own * wa_own;
    if (tid < 32) ((float4*)qrow)[tid] = __ldg((const float4*)(q + b * H_) + tid);
    #pragma unroll
    for (int o = 16; o; o >>= 1) {
        s0 += __shfl_xor_sync(0xFFFFFFFFu, s0, o);
        s2 += __shfl_xor_sync(0xFFFFFFFFu, s2, o);
    }
    if (lane == 0) { red[warp] = s0; red[8 + warp] = s2; }
    __syncthreads();
    if (tid == 0) {
        scl[0] = gv[0] / sqrtf(red[0] + red[1] + red[2] + red[3]);
        scl[2] = ga[0] / sqrtf(red[8] + red[9] + red[10] + red[11]);
        scl[3] = ba[0];
    }
    __syncthreads();
    const float sv = scl[0], sa = scl[2];

    // ---- stage W (scaled, tf32 rna-rounded) ----
    for (int i = tid; i < 4096; i += THREADS) {
        int p = i >> 5, c4 = i & 31;
        float4 a = __ldg((const float4*)Wv + i);
        a.x = f2tf(sv * a.x); a.y = f2tf(sv * a.y);
        a.z = f2tf(sv * a.z); a.w = f2tf(sv * a.w);
        *(float4*)(sm + F_W + p * LDSF + c4 * 4) = a;
    }

    // ---- qproj from staged Wq (also Wq norm in the same pass) ----
    cp_wait1();
    __syncthreads();
    float dotv = 0.f, s1 = 0.f;
    {
        const float* wr = sm + F_V1 + tid * LDSF;
        #pragma unroll 8
        for (int h = 0; h < H_; h++) {
            float w = wr[h];
            dotv += w * qrow[h];
            s1 += w * w;
        }
    }
    float s1r = s1;
    #pragma unroll
    for (int o = 16; o; o >>= 1) s1r += __shfl_xor_sync(0xFFFFFFFFu, s1r, o);
    if (lane == 0) red[warp] = s1r;
    __syncthreads();
    if (tid == 0) scl[1] = gq[0] / sqrtf(red[0] + red[1] + red[2] + red[3]);
    __syncthreads();
    {
        float2 qv;
        qv.x = scl[1] * dotv + __ldg(&bq[tid]) + __ldg(&bv[tid]);
        qv.y = sa * wa_own;
        qwas[tid] = qv;
    }
    __syncthreads();   // everyone done reading V1 (Wq)

    // ---- group 2: v tile1 -> V1 ----
    for (int i = tid; i < 4096; i += THREADS) {
        int row = i >> 5, c4 = i & 31;
        cp16(sb + (F_V1 + row * LDSF) * 4 + c4 * 16, vsrc + (size_t)(128 + row) * H_ + c4 * 4);
    }
    cp_commit();

    // ---- ldmatrix static address offsets (bytes) ----
    const int j = lane >> 3;
    int aoff[4], boff[4];
    #pragma unroll
    for (int m = 0; m < 4; m++) {
        int row = mi * 64 + m * 16 + ((j & 1) << 3) + (lane & 7);
        aoff[m] = row * LDSB + ((j >> 1) << 4);
    }
    #pragma unroll
    for (int p = 0; p < 4; p++) {
        int row = ni * 64 + p * 16 + ((j >> 1) << 3) + (lane & 7);
        boff[p] = (F_W * 4) + row * LDSB + ((j & 1) << 4);
    }

    float M = -INFINITY, S = 0.f, attp = 0.f;

    for (int t = 0; t < NTILES; t++) {
        if (t < NTILES - 1) cp_wait1(); else cp_wait0();
        __syncthreads();
        const uint32_t vb = sb + ((t & 1) ? F_V1 : F_V0) * 4;
        const float*   Vg = sm + ((t & 1) ? F_V1 : F_V0);

        // ---- GEMM 128x128x128 (4 warps x 64x64), tf32 mma ----
        float acc[4][8][4];
        #pragma unroll
        for (int m = 0; m < 4; m++)
            #pragma unroll
            for (int n = 0; n < 8; n++)
                #pragma unroll
                for (int x = 0; x < 4; x++) acc[m][n][x] = 0.f;

        #pragma unroll
        for (int k = 0; k < 16; k++) {
            uint32_t a[4][4], bb[4][4];
            #pragma unroll
            for (int m = 0; m < 4; m++) ldsm4(a[m], vb + aoff[m] + 32 * k);
            #pragma unroll
            for (int p = 0; p < 4; p++) ldsm4(bb[p], sb + boff[p] + 32 * k);
            #pragma unroll
            for (int m = 0; m < 4; m++)
                #pragma unroll
                for (int n = 0; n < 8; n++)
                    mma_tf32(acc[m][n], a[m][0], a[m][1], a[m][2], a[m][3],
                             bb[n >> 1][(n & 1) * 2], bb[n >> 1][(n & 1) * 2 + 1]);
        }

        // ---- epilogue: relu + wa dot -> row partials ----
        float4 qw[8];
        #pragma unroll
        for (int n = 0; n < 8; n++)
            qw[n] = *(const float4*)&qwas[ni * 64 + n * 8 + 2 * t4];
        #pragma unroll
        for (int m = 0; m < 4; m++) {
            float pl0 = 0.f, pl1 = 0.f;
            #pragma unroll
            for (int n = 0; n < 8; n++) {
                pl0 += fmaxf(acc[m][n][0] + qw[n].x, 0.f) * qw[n].y
                     + fmaxf(acc[m][n][1] + qw[n].z, 0.f) * qw[n].w;
                pl1 += fmaxf(acc[m][n][2] + qw[n].x, 0.f) * qw[n].y
                     + fmaxf(acc[m][n][3] + qw[n].z, 0.f) * qw[n].w;
            }
            pl0 += __shfl_xor_sync(0xFFFFFFFFu, pl0, 1);
            pl0 += __shfl_xor_sync(0xFFFFFFFFu, pl0, 2);
            pl1 += __shfl_xor_sync(0xFFFFFFFFu, pl1, 1);
            pl1 += __shfl_xor_sync(0xFFFFFFFFu, pl1, 2);
            if (t4 == 0) {
                const int g = lane >> 2;
                const int r0 = mi * 64 + m * 16 + g;
                lgp[r0 * 2 + ni]       = pl0;
                lgp[(r0 + 8) * 2 + ni] = pl1;
            }
        }
        __syncthreads();

        // ---- combine + mask -> logit; warp max ----
        float l = lgp[tid * 2] + lgp[tid * 2 + 1] + scl[3]
                + (1.f - __ldg(&mask[(size_t)b * N_ + t * 128 + tid])) * NEGC;
        lsm[t * 128 + tid] = l;
        float x = l;
        #pragma unroll
        for (int o = 16; o; o >>= 1) x = fmaxf(x, __shfl_xor_sync(0xFFFFFFFFu, x, o));
        if (lane == 0) bc[warp] = x;
        __syncthreads();

        float Mn = fmaxf(M, fmaxf(fmaxf(bc[0], bc[1]), fmaxf(bc[2], bc[3])));
        float r  = __expf(M - Mn);
        float e  = __expf(l - Mn);
        we[tid] = e;
        #pragma unroll
        for (int o = 16; o; o >>= 1) e += __shfl_xor_sync(0xFFFFFFFFu, e, o);
        if (lane == 0) bc[8 + warp] = e;
        __syncthreads();
        S = S * r + (bc[8] + bc[9] + bc[10] + bc[11]);
        M = Mn;

        // ---- att update: thread owns column h = tid, raw fp32 V ----
        float a0 = 0.f, a1 = 0.f, a2 = 0.f, a3 = 0.f;
        #pragma unroll 8
        for (int row = 0; row < 128; row += 4) {
            a0 += we[row]     * Vg[row * LDSF + tid];
            a1 += we[row + 1] * Vg[(row + 1) * LDSF + tid];
            a2 += we[row + 2] * Vg[(row + 2) * LDSF + tid];
            a3 += we[row + 3] * Vg[(row + 3) * LDSF + tid];
        }
        attp = attp * r + ((a0 + a1) + (a2 + a3));
        __syncthreads();   // done with this V buffer

        // ---- prefetch tile t+2 into this buffer ----
        if (t + 2 < NTILES) {
            const float* src = vsrc + (size_t)(t + 2) * 128 * H_;
            const uint32_t dstb = sb + ((t & 1) ? F_V1 : F_V0) * 4;
            for (int i = tid; i < 4096; i += THREADS) {
                int row = i >> 5, c4 = i & 31;
                cp16(dstb + (row * LDSF) * 4 + c4 * 16, src + row * H_ + c4 * 4);
            }
        }
        cp_commit();  // keep group accounting uniform
    }

    // ---- finals ----
    const float invS = 1.f / S;
    out_att[b * H_ + tid] = attp * invS;
    #pragma unroll 4
    for (int n = tid; n < N_; n += THREADS) {
        out_w[(size_t)b * N_ + n] = __expf(lsm[n] - M) * invS;
    }
}

// ---------------------------------------------------------------------------
extern "C" void kernel_launch(void* const* d_in, const int* in_sizes, int n_in,
                              void* d_out, int out_size) {
    const float* v    = (const float*)d_in[0];
    const float* q    = (const float*)d_in[1];
    const float* mask = (const float*)d_in[2];
    const float* Wv   = (const float*)d_in[3];
    const float* bv   = (const float*)d_in[4];
    const float* gv   = (const float*)d_in[5];
    const float* Wq   = (const float*)d_in[6];
    const float* bq   = (const float*)d_in[7];
    const float* gq   = (const float*)d_in[8];
    const float* Wa   = (const float*)d_in[9];
    const float* ba   = (const float*)d_in[10];
    const float* ga   = (const float*)d_in[11];

    float* out     = (float*)d_out;
    float* out_att = out;              // [B, H]
    float* out_w   = out + B_ * H_;    // [B, N, 1]

    const int smem_bytes = SMEM_FLOATS * sizeof(float);
    cudaFuncSetAttribute(main_kernel, cudaFuncAttributeMaxDynamicSharedMemorySize, smem_bytes);

    main_kernel<<<B_, THREADS, smem_bytes>>>(v, q, mask, Wv, bv, gv, Wq, bq, gq,
                                             Wa, ba, ga, out_att, out_w);
}

// round 5
// speedup vs baseline: 2.3753x; 1.3194x over previous
#include <cuda_runtime.h>
#include <math.h>
#include <stdint.h>

#define B_ 128
#define N_ 4096
#define H_ 128
#define P_ 128
#define NTILES 32
#define THREADS 256
#define NEGC (-10000.0f)

// padded row stride: 132 floats = 528 bytes (33*16B -> LDSM conflict-free)
#define LDSF 132
#define LDSB 528

// ---------------- smem layout (float offsets) ----------------
#define F_W     0                      // 128*132 = 16896 (scaled tf32 Wv)
#define F_V0    16896                  // 16896
#define F_V1    (F_V0 + 16896)         // 16896 (also Wq staging in setup)
#define F_LSM   (F_V1 + 16896)         // 4096 logits
#define F_QW    (F_LSM + 4096)         // 256 (float2 qwas[128])
#define F_WE    (F_QW + 256)           // 128
#define F_LGP   (F_WE + 128)           // 512 (double-buffered 2 x 256)
#define F_BC    (F_LGP + 512)          // 16
#define F_RED   (F_BC + 16)            // 16
#define F_SCL   (F_RED + 16)           // 8
#define F_QROW  (F_SCL + 8)            // 128
#define SMEM_FLOATS (F_QROW + 128)     // 55848 floats = 223392 B

// ---------------- helpers ----------------
__device__ __forceinline__ float f2tf(float x) {
    uint32_t r;
    asm("cvt.rna.tf32.f32 %0, %1;" : "=r"(r) : "f"(x));
    return __uint_as_float(r);
}

__device__ __forceinline__ void mma_tf32(float* d,
                                         uint32_t a0, uint32_t a1, uint32_t a2, uint32_t a3,
                                         uint32_t b0, uint32_t b1) {
    asm volatile(
        "mma.sync.aligned.m16n8k8.row.col.f32.tf32.tf32.f32 "
        "{%0,%1,%2,%3}, {%4,%5,%6,%7}, {%8,%9}, {%0,%1,%2,%3};"
        : "+f"(d[0]), "+f"(d[1]), "+f"(d[2]), "+f"(d[3])
        : "r"(a0), "r"(a1), "r"(a2), "r"(a3), "r"(b0), "r"(b1));
}

__device__ __forceinline__ void ldsm4(uint32_t* r, uint32_t addr) {
    asm volatile("ldmatrix.sync.aligned.m8n8.x4.shared.b16 {%0,%1,%2,%3}, [%4];"
                 : "=r"(r[0]), "=r"(r[1]), "=r"(r[2]), "=r"(r[3]) : "r"(addr));
}

__device__ __forceinline__ void cp16(uint32_t dst, const void* src) {
    asm volatile("cp.async.cg.shared.global [%0], [%1], 16;" :: "r"(dst), "l"(src));
}
__device__ __forceinline__ void cp_commit() { asm volatile("cp.async.commit_group;" ::); }
__device__ __forceinline__ void cp_wait1()  { asm volatile("cp.async.wait_group 1;" ::); }
__device__ __forceinline__ void cp_wait0()  { asm volatile("cp.async.wait_group 0;" ::); }

#define BAR_SYNC(id, cnt)   asm volatile("bar.sync %0, %1;"   :: "r"(id), "r"(cnt) : "memory")
#define BAR_ARRIVE(id, cnt) asm volatile("bar.arrive %0, %1;" :: "r"(id), "r"(cnt) : "memory")
#define MEMBAR_CTA()        asm volatile("membar.cta;" ::: "memory")

// ---------------------------------------------------------------------------
// One CTA per batch row. 256 threads:
//   warps 0-3 (GEMM group): 64x64 ldsm/mma tf32 blocks + relu-wa partials
//   warps 4-7 (helper group): logits combine + online softmax + att update +
//                             cp.async V prefetch, overlapped with GEMM(t+1).
// ---------------------------------------------------------------------------
__global__ void __launch_bounds__(THREADS, 1)
main_kernel(const float* __restrict__ v,
            const float* __restrict__ q,
            const float* __restrict__ mask,
            const float* __restrict__ Wv,
            const float* __restrict__ bv,
            const float* __restrict__ gv,
            const float* __restrict__ Wq,
            const float* __restrict__ bq,
            const float* __restrict__ gq,
            const float* __restrict__ Wa,
            const float* __restrict__ ba,
            const float* __restrict__ ga,
            float* __restrict__ out_att,
            float* __restrict__ out_w) {
    const int b    = blockIdx.x;
    const int tid  = threadIdx.x;
    const int warp = tid >> 5;
    const int lane = tid & 31;

    extern __shared__ float sm[];
    const uint32_t sb = (uint32_t)__cvta_generic_to_shared(sm);
    float*  lsm  = sm + F_LSM;
    float2* qwas = (float2*)(sm + F_QW);
    float*  we   = sm + F_WE;
    float*  lgp  = sm + F_LGP;
    float*  bc   = sm + F_BC;
    float*  red  = sm + F_RED;
    float*  scl  = sm + F_SCL;
    float*  qrow = sm + F_QROW;

    const float* vsrc = v + (size_t)b * N_ * H_;

    // =================== setup (all 256 threads) ===================
    // stage Wq raw -> V1 (plain LDG/STS); Wv/Wa norms; q row
    float s0 = 0.f;
    for (int i = tid; i < 4096; i += THREADS) {
        int row = i >> 5, c4 = i & 31;
        float4 w4 = __ldg((const float4*)Wq + i);
        *(float4*)(sm + F_V1 + row * LDSF + c4 * 4) = w4;
        float4 a = __ldg((const float4*)Wv + i);
        s0 += a.x * a.x + a.y * a.y + a.z * a.z + a.w * a.w;
    }
    const float wa_own = (tid < P_) ? __ldg(&Wa[tid]) : 0.f;
    float s2 = wa_own * wa_own;
    if (tid < 32) ((float4*)qrow)[tid] = __ldg((const float4*)(q + b * H_) + tid);
    #pragma unroll
    for (int o = 16; o; o >>= 1) {
        s0 += __shfl_xor_sync(0xFFFFFFFFu, s0, o);
        s2 += __shfl_xor_sync(0xFFFFFFFFu, s2, o);
    }
    if (lane == 0) { red[warp] = s0; red[8 + warp] = s2; }
    __syncthreads();
    if (tid == 0) {
        float a = 0.f, c = 0.f;
        #pragma unroll
        for (int i = 0; i < 8; i++) { a += red[i]; c += red[8 + i]; }
        scl[0] = gv[0] / sqrtf(a);
        scl[2] = ga[0] / sqrtf(c);
        scl[3] = ba[0];
    }
    __syncthreads();
    const float sv = scl[0], sa = scl[2];

    // stage W (scaled, tf32 rna-rounded)
    for (int i = tid; i < 4096; i += THREADS) {
        int p = i >> 5, c4 = i & 31;
        float4 a = __ldg((const float4*)Wv + i);
        a.x = f2tf(sv * a.x); a.y = f2tf(sv * a.y);
        a.z = f2tf(sv * a.z); a.w = f2tf(sv * a.w);
        *(float4*)(sm + F_W + p * LDSF + c4 * 4) = a;
    }

    // qproj + Wq norm from staged rows (threads 0-127 own one row each)
    float dotv = 0.f, s1 = 0.f;
    if (tid < P_) {
        const float* wr = sm + F_V1 + tid * LDSF;
        #pragma unroll 8
        for (int h = 0; h < H_; h++) {
            float w = wr[h];
            dotv += w * qrow[h];
            s1 += w * w;
        }
    }
    #pragma unroll
    for (int o = 16; o; o >>= 1) s1 += __shfl_xor_sync(0xFFFFFFFFu, s1, o);
    if (lane == 0 && warp < 4) red[warp] = s1;
    __syncthreads();
    if (tid == 0) scl[1] = gq[0] / sqrtf(red[0] + red[1] + red[2] + red[3]);
    __syncthreads();
    if (tid < P_) {
        float2 qv;
        qv.x = scl[1] * dotv + __ldg(&bq[tid]) + __ldg(&bv[tid]);
        qv.y = sa * wa_own;
        qwas[tid] = qv;
    }
    __syncthreads();   // everyone done with V1 (Wq staging)
    const float ba0 = scl[3];

    // =================== split: GEMM group / helper group ===================
    if (warp < 4) {
        // ---------------- GEMM group ----------------
        const int t4 = lane & 3;
        const int mi = warp & 1;
        const int ni = warp >> 1;
        const int j  = lane >> 3;
        int aoff[4], boff[4];
        #pragma unroll
        for (int m = 0; m < 4; m++) {
            int row = mi * 64 + m * 16 + ((j & 1) << 3) + (lane & 7);
            aoff[m] = row * LDSB + ((j >> 1) << 4);
        }
        #pragma unroll
        for (int p = 0; p < 4; p++) {
            int row = ni * 64 + p * 16 + ((j >> 1) << 3) + (lane & 7);
            boff[p] = (F_W * 4) + row * LDSB + ((j & 1) << 4);
        }

        float4 qw[8];
        #pragma unroll
        for (int n = 0; n < 8; n++)
            qw[n] = *(const float4*)&qwas[ni * 64 + n * 8 + 2 * t4];

        for (int t = 0; t < NTILES; t++) {
            BAR_SYNC(1, 256);                       // V(t) ready
            const uint32_t vb = sb + ((t & 1) ? F_V1 : F_V0) * 4;

            float acc[4][8][4];
            #pragma unroll
            for (int m = 0; m < 4; m++)
                #pragma unroll
                for (int n = 0; n < 8; n++)
                    #pragma unroll
                    for (int x = 0; x < 4; x++) acc[m][n][x] = 0.f;

            #pragma unroll
            for (int k = 0; k < 16; k++) {
                uint32_t a[4][4], bb[4][4];
                #pragma unroll
                for (int m = 0; m < 4; m++) ldsm4(a[m], vb + aoff[m] + 32 * k);
                #pragma unroll
                for (int p = 0; p < 4; p++) ldsm4(bb[p], sb + boff[p] + 32 * k);
                #pragma unroll
                for (int m = 0; m < 4; m++)
                    #pragma unroll
                    for (int n = 0; n < 8; n++)
                        mma_tf32(acc[m][n], a[m][0], a[m][1], a[m][2], a[m][3],
                                 bb[n >> 1][(n & 1) * 2], bb[n >> 1][(n & 1) * 2 + 1]);
            }

            // relu + wa dot -> row partials into lgp[t&1]
            float* lgpb = lgp + (t & 1) * 256;
            #pragma unroll
            for (int m = 0; m < 4; m++) {
                float pl0 = 0.f, pl1 = 0.f;
                #pragma unroll
                for (int n = 0; n < 8; n++) {
                    pl0 += fmaxf(acc[m][n][0] + qw[n].x, 0.f) * qw[n].y
                         + fmaxf(acc[m][n][1] + qw[n].z, 0.f) * qw[n].w;
                    pl1 += fmaxf(acc[m][n][2] + qw[n].x, 0.f) * qw[n].y
                         + fmaxf(acc[m][n][3] + qw[n].z, 0.f) * qw[n].w;
                }
                pl0 += __shfl_xor_sync(0xFFFFFFFFu, pl0, 1);
                pl0 += __shfl_xor_sync(0xFFFFFFFFu, pl0, 2);
                pl1 += __shfl_xor_sync(0xFFFFFFFFu, pl1, 1);
                pl1 += __shfl_xor_sync(0xFFFFFFFFu, pl1, 2);
                if (t4 == 0) {
                    const int gg = lane >> 2;
                    const int r0 = mi * 64 + m * 16 + gg;
                    lgpb[r0 * 2 + ni]       = pl0;
                    lgpb[(r0 + 8) * 2 + ni] = pl1;
                }
            }
            MEMBAR_CTA();
            BAR_ARRIVE(2, 256);                     // lgp(t) ready
        }
    } else {
        // ---------------- helper group ----------------
        const int ht = tid - 128;     // 0..127, owns column ht
        const int hw = warp - 4;      // 0..3

        // prefetch V0, V1
        for (int i = ht; i < 4096; i += 128) {
            int row = i >> 5, c4 = i & 31;
            cp16(sb + (F_V0 + row * LDSF) * 4 + c4 * 16, vsrc + row * H_ + c4 * 4);
        }
        cp_commit();
        for (int i = ht; i < 4096; i += 128) {
            int row = i >> 5, c4 = i & 31;
            cp16(sb + (F_V1 + row * LDSF) * 4 + c4 * 16,
                 vsrc + (size_t)(128 + row) * H_ + c4 * 4);
        }
        cp_commit();
        cp_wait1();                                  // V0 done
        MEMBAR_CTA();
        BAR_ARRIVE(1, 256);                          // V(0) ready

        float M = -INFINITY, S = 0.f, attp = 0.f;

        for (int t = 0; t < NTILES; t++) {
            const float mkv = __ldg(&mask[(size_t)b * N_ + t * 128 + ht]);
            BAR_SYNC(2, 256);                        // lgp(t) ready
            cp_wait0();                              // V(t+1) complete
            MEMBAR_CTA();
            if (t < NTILES - 1) BAR_ARRIVE(1, 256);  // release GEMM(t+1)

            // combine partials + mask -> logit
            const float* lgpb = lgp + (t & 1) * 256;
            float l = lgpb[ht * 2] + lgpb[ht * 2 + 1] + ba0 + (1.f - mkv) * NEGC;
            lsm[t * 128 + ht] = l;

            float x = l;
            #pragma unroll
            for (int o = 16; o; o >>= 1) x = fmaxf(x, __shfl_xor_sync(0xFFFFFFFFu, x, o));
            if (lane == 0) bc[hw] = x;
            BAR_SYNC(3, 128);
            float Mn = fmaxf(M, fmaxf(fmaxf(bc[0], bc[1]), fmaxf(bc[2], bc[3])));
            float r  = __expf(M - Mn);
            float e  = __expf(l - Mn);
            we[ht] = e;
            #pragma unroll
            for (int o = 16; o; o >>= 1) e += __shfl_xor_sync(0xFFFFFFFFu, e, o);
            if (lane == 0) bc[8 + hw] = e;
            BAR_SYNC(3, 128);                        // we[] + sums visible
            S = S * r + (bc[8] + bc[9] + bc[10] + bc[11]);
            M = Mn;

            // att update from V(t) (raw fp32 in smem)
            const float* Vg = sm + ((t & 1) ? F_V1 : F_V0);
            float a0 = 0.f, a1 = 0.f, a2 = 0.f, a3 = 0.f;
            #pragma unroll 8
            for (int row = 0; row < 128; row += 4) {
                a0 += we[row]     * Vg[row * LDSF + ht];
                a1 += we[row + 1] * Vg[(row + 1) * LDSF + ht];
                a2 += we[row + 2] * Vg[(row + 2) * LDSF + ht];
                a3 += we[row + 3] * Vg[(row + 3) * LDSF + ht];
            }
            attp = attp * r + ((a0 + a1) + (a2 + a3));
            BAR_SYNC(3, 128);                        // att reads done

            // prefetch V(t+2) into buf(t&1)
            if (t + 2 < NTILES) {
                const float* src = vsrc + (size_t)(t + 2) * 128 * H_;
                const uint32_t dstb = sb + ((t & 1) ? F_V1 : F_V0) * 4;
                for (int i = ht; i < 4096; i += 128) {
                    int row = i >> 5, c4 = i & 31;
                    cp16(dstb + (row * LDSF) * 4 + c4 * 16, src + row * H_ + c4 * 4);
                }
            }
            cp_commit();
        }

        if (ht == 0) { red[0] = M; red[1] = 1.f / S; }
        out_att[b * H_ + ht] = attp / S;
    }

    // =================== finals (all 256) ===================
    __syncthreads();
    const float Mf = red[0], invS = red[1];
    #pragma unroll 4
    for (int n = tid; n < N_; n += THREADS) {
        out_w[(size_t)b * N_ + n] = __expf(lsm[n] - Mf) * invS;
    }
}

// ---------------------------------------------------------------------------
extern "C" void kernel_launch(void* const* d_in, const int* in_sizes, int n_in,
                              void* d_out, int out_size) {
    const float* v    = (const float*)d_in[0];
    const float* q    = (const float*)d_in[1];
    const float* mask = (const float*)d_in[2];
    const float* Wv   = (const float*)d_in[3];
    const float* bv   = (const float*)d_in[4];
    const float* gv   = (const float*)d_in[5];
    const float* Wq   = (const float*)d_in[6];
    const float* bq   = (const float*)d_in[7];
    const float* gq   = (const float*)d_in[8];
    const float* Wa   = (const float*)d_in[9];
    const float* ba   = (const float*)d_in[10];
    const float* ga   = (const float*)d_in[11];

    float* out     = (float*)d_out;
    float* out_att = out;              // [B, H]
    float* out_w   = out + B_ * H_;    // [B, N, 1]

    const int smem_bytes = SMEM_FLOATS * sizeof(float);
    cudaFuncSetAttribute(main_kernel, cudaFuncAttributeMaxDynamicSharedMemorySize, smem_bytes);

    main_kernel<<<B_, THREADS, smem_bytes>>>(v, q, mask, Wv, bv, gv, Wq, bq, gq,
                                             Wa, ba, ga, out_att, out_w);
}